// round 3
// baseline (speedup 1.0000x reference)
#include <cuda_runtime.h>
#include <math.h>
#include <stdint.h>

#define DIMD 768
#define NTOK 1024
#define NB   16
#define MTOT (NB*NTOK)   // 16384

// ---------------- scratch (static device globals) --------------------------
__device__ float g_avg[NB*DIMD];
__device__ float g_sq [MTOT];
__device__ float g_m  [MTOT];
__device__ float g_Ap [MTOT*DIMD];     // A in P-format (mma A-fragment order)
__device__ float g_Ab [MTOT*DIMD];     // A in B-format (mma B-fragment order)
__device__ float g_rm0[MTOT*DIMD];     // m1 (layer1 out); later x*l3 (layer3 out)
__device__ float g_rm1[MTOT*DIMD];     // t  (layer2 out)
__device__ float g_wB [5*DIMD*DIMD];   // weights in B-format
#define W1B 0
#define W2B (2*DIMD*DIMD)
#define W3B (3*DIMD*DIMD)
#define W4B (4*DIMD*DIMD)

// ---------------- helpers ---------------------------------------------------
__device__ __forceinline__ float tf32r(float x){
    unsigned u; asm("cvt.rna.tf32.f32 %0, %1;" : "=r"(u) : "f"(x));
    return __uint_as_float(u);
}
__device__ __forceinline__ float gelu_exact(float v){ return v * normcdff(v); }

__device__ __forceinline__ uint32_t smem_u32(const void* p){
    uint32_t a; asm("{ .reg .u64 t; cvta.to.shared.u64 t, %1; cvt.u32.u64 %0, t; }" : "=r"(a) : "l"(p));
    return a;
}
// P-format: per 16(row)x8(k) subtile, 32 lanes x float4 {A[r][k],A[r+8][k],A[r][k+4],A[r+8][k+4]}
__device__ __forceinline__ int addrP(int r, int k, int K){
    return ((r>>4)*(K>>3) + (k>>3))*128 + ((r&7)*4 + (k&3))*4 + ((r>>3)&1) + (((k>>2)&1)<<1);
}
// B-format: per 8(n)x8(k) subtile, 32 lanes x float2 {B[k][n],B[k+4][n]} (B[k][n] = w[k][n])
__device__ __forceinline__ int addrB(int n, int k, int K){
    return ((n>>3)*(K>>3) + (k>>3))*64 + ((n&7)*4 + (k&3))*2 + ((k>>2)&1);
}
__device__ __forceinline__ void cpa16(uint32_t dst, const float* src){
    asm volatile("cp.async.cg.shared.global [%0], [%1], 16;" :: "r"(dst), "l"(src));
}
__device__ __forceinline__ void cpa_commit(){ asm volatile("cp.async.commit_group;"); }
__device__ __forceinline__ void cpa_wait1(){ asm volatile("cp.async.wait_group 1;"); }

__device__ __forceinline__ void mma8(float* cc, const float* a, const float* b){
    asm volatile("mma.sync.aligned.m16n8k8.row.col.f32.tf32.tf32.f32 "
       "{%0,%1,%2,%3},{%4,%5,%6,%7},{%8,%9},{%0,%1,%2,%3};"
       : "+f"(cc[0]),"+f"(cc[1]),"+f"(cc[2]),"+f"(cc[3])
       : "r"(__float_as_uint(a[0])),"r"(__float_as_uint(a[1])),
         "r"(__float_as_uint(a[2])),"r"(__float_as_uint(a[3])),
         "r"(__float_as_uint(b[0])),"r"(__float_as_uint(b[1])));
}

// smem: 3 stages x (A 16KB + B 16KB) = 96KB dynamic
#define STG_A 16384u
#define STG_B 16384u
#define SB_OFF 49152u
#define DSMEM_SZ 98304

// ---------------------------------------------------------------- k_avg
__global__ void k_avg(const float* __restrict__ x){
    int gid = blockIdx.x*256 + threadIdx.x;
    int b = gid / DIMD, d = gid % DIMD;
    const float* p = x + (size_t)b*NTOK*DIMD + d;
    float s = 0.f;
    #pragma unroll 8
    for (int n = 0; n < NTOK; n++) s += p[n*DIMD];
    g_avg[gid] = s * (1.0f/NTOK);
}

// ---------------------------------------------------------------- k_ln
// A = tf32(avg * sigmoid(LN(x))) -> g_Ap, g_Ab ; g_sq=|A|^2 ; g_m=0
__global__ void k_ln(const float* __restrict__ x,
                     const float* __restrict__ gamma,
                     const float* __restrict__ beta){
    int tok = blockIdx.x;
    int b = tok >> 10;
    const float* xp = x + (size_t)tok*DIMD;
    int t = threadIdx.x;
    float v[3]; float s=0.f, s2=0.f;
    #pragma unroll
    for (int i=0;i<3;i++){ v[i]=xp[t+256*i]; s+=v[i]; s2+=v[i]*v[i]; }
    __shared__ float red[16];
    #pragma unroll
    for (int o=16;o;o>>=1){ s+=__shfl_xor_sync(~0u,s,o); s2+=__shfl_xor_sync(~0u,s2,o); }
    int w = t>>5;
    if ((t&31)==0){ red[w]=s; red[w+8]=s2; }
    __syncthreads();
    if (t<32){
        float a=(t<8)?red[t]:0.f, bb=(t<8)?red[t+8]:0.f;
        #pragma unroll
        for (int o=4;o;o>>=1){ a+=__shfl_xor_sync(~0u,a,o); bb+=__shfl_xor_sync(~0u,bb,o); }
        if (t==0){ red[0]=a; red[1]=bb; }
    }
    __syncthreads();
    float mu  = red[0]*(1.f/DIMD);
    float var = red[1]*(1.f/DIMD) - mu*mu;
    float rs  = rsqrtf(var + 1e-5f);
    float asq = 0.f;
    const float* av = g_avg + b*DIMD;
    #pragma unroll
    for (int i=0;i<3;i++){
        int d = t + 256*i;
        float y  = (v[i]-mu)*rs*gamma[d] + beta[d];
        float sg = 1.f/(1.f+expf(-y));
        float a  = tf32r(av[d]*sg);
        g_Ap[addrP(tok,d,DIMD)] = a;
        g_Ab[addrB(tok,d,DIMD)] = a;
        asq += a*a;
    }
    #pragma unroll
    for (int o=16;o;o>>=1) asq += __shfl_xor_sync(~0u,asq,o);
    __syncthreads();
    if ((t&31)==0) red[w]=asq;
    __syncthreads();
    if (t==0){
        float a=0.f;
        #pragma unroll
        for (int i=0;i<8;i++) a+=red[i];
        g_sq[tok]=a;
        g_m[tok]=0.f;
    }
}

// ---------------------------------------------------------------- k_tr
// weights [K][768] row-major -> B-format, tf32-rounded
__global__ void k_tr(const float* __restrict__ w, float* __restrict__ wB, int K){
    int n = blockIdx.y*256 + threadIdx.x;
    int k = blockIdx.x;
    wB[addrB(n,k,K)] = tf32r(w[(size_t)k*DIMD + n]);
}

// ---------------------------------------------------------------- k_gemm
// MODE 0: A = P-format (cp.async).  MODE 1: A = row-major raw (LDG+cvt+STS).
// MODE 2: k<768 from P-format pA; k>=768 from row-major x + g_m (cvt).
// EPI 0: gelu   1: gelu*x*m1r   2: gelu*x
template<int MODE, int EPI>
__global__ void __launch_bounds__(256) k_gemm(
    const float* __restrict__ pA, const float* __restrict__ pB,
    const float* __restrict__ bias, const float* __restrict__ x,
    const float* __restrict__ m1r, float* __restrict__ Cout, int Ktot)
{
    extern __shared__ float dsm[];
    uint32_t sA = smem_u32(dsm);
    uint32_t sB = sA + SB_OFF;
    int tid = threadIdx.x, lane = tid&31;
    int wm = (tid>>5)&1, wn = tid>>6;
    int r = lane>>2, c = lane&3;
    int nb = blockIdx.x, mb = blockIdx.y;
    const int KT = Ktot/32;

    float acc[4][4][4];
    #pragma unroll
    for (int a=0;a<4;a++)
      #pragma unroll
      for (int b=0;b<4;b++)
        #pragma unroll
        for (int e=0;e<4;e++) acc[a][b][e]=0.f;

    auto load_stage = [&](int kt){
        int st = kt % 3;
        uint32_t dA = sA + st*STG_A;
        uint32_t dB = sB + st*STG_B;
        int k0 = kt*32;
        int j0 = k0>>3;
        // B tile: 16 n-subtile-blocks x 4 k-subtiles
        #pragma unroll
        for (int it=0; it<4; it++){
            int idx = it*256 + tid;
            int nblk = idx>>6, rem = idx&63;
            cpa16(dB + idx*16, pB + ((size_t)(nb*16+nblk)*(Ktot>>3) + j0)*64 + rem*4);
        }
        // A tile
        if (MODE==0 || (MODE==2 && k0 < DIMD)){
            int KA = (MODE==0)? Ktot : DIMD;
            #pragma unroll
            for (int it=0; it<4; it++){
                int idx = it*256 + tid;
                int i = idx>>7, rem = idx&127;
                cpa16(dA + idx*16, pA + ((size_t)(mb*8+i)*(KA>>3) + (k0>>3))*128 + rem*4);
            }
        } else {
            #pragma unroll
            for (int it=0; it<4; it++){
                int idx = it*256 + tid;
                int row = idx>>3, k4 = idx&7;
                int rg = mb*128 + row;
                int kk = k0 + k4*4;
                float4 v;
                if (MODE==2){
                    v = *(const float4*)(x + (size_t)rg*DIMD + (kk-DIMD));
                    float mm = g_m[rg];
                    v.x+=mm; v.y+=mm; v.z+=mm; v.w+=mm;
                } else {
                    v = *(const float4*)(pA + (size_t)rg*DIMD + kk);
                }
                v.x=tf32r(v.x); v.y=tf32r(v.y); v.z=tf32r(v.z); v.w=tf32r(v.w);
                uint32_t base = dA + (((row>>4)*4 + (k4>>1))<<9)
                              + ((((row>>3)&1) + ((k4&1)<<1))<<2);
                uint32_t lb = (row&7)*4;
                asm volatile("st.shared.f32 [%0], %1;" :: "r"(base+(lb+0)*16), "f"(v.x));
                asm volatile("st.shared.f32 [%0], %1;" :: "r"(base+(lb+1)*16), "f"(v.y));
                asm volatile("st.shared.f32 [%0], %1;" :: "r"(base+(lb+2)*16), "f"(v.z));
                asm volatile("st.shared.f32 [%0], %1;" :: "r"(base+(lb+3)*16), "f"(v.w));
            }
        }
        cpa_commit();
    };

    load_stage(0); load_stage(1);
    for (int kt=0; kt<KT; kt++){
        cpa_wait1();
        __syncthreads();
        if (kt+2 < KT) load_stage(kt+2); else cpa_commit();
        int st = kt % 3;
        uint32_t bA = sA + st*STG_A;
        uint32_t bB = sB + st*STG_B;
        #pragma unroll
        for (int jj=0;jj<4;jj++){
            float4 af[4]; float2 bf[4];
            #pragma unroll
            for (int mt=0;mt<4;mt++){
                uint32_t a = bA + ((((wm*4+mt)*4+jj))<<9) + (lane<<4);
                asm volatile("ld.shared.v4.f32 {%0,%1,%2,%3},[%4];"
                  : "=f"(af[mt].x),"=f"(af[mt].y),"=f"(af[mt].z),"=f"(af[mt].w) : "r"(a));
            }
            #pragma unroll
            for (int nt=0;nt<4;nt++){
                uint32_t a = bB + ((((wn*4+nt)*4+jj))<<8) + (lane<<3);
                asm volatile("ld.shared.v2.f32 {%0,%1},[%2];"
                  : "=f"(bf[nt].x),"=f"(bf[nt].y) : "r"(a));
            }
            #pragma unroll
            for (int mt=0;mt<4;mt++)
                #pragma unroll
                for (int nt=0;nt<4;nt++)
                    mma8(acc[mt][nt], &af[mt].x, &bf[nt].x);
        }
    }

    // epilogue (row-major float2 stores)
    #pragma unroll
    for (int mt=0; mt<4; mt++){
        #pragma unroll
        for (int i2=0; i2<2; i2++){
            int rg = mb*128 + wm*64 + mt*16 + r + i2*8;
            #pragma unroll
            for (int nt=0; nt<4; nt++){
                int cg = nb*128 + wn*32 + nt*8 + 2*c;
                float v0 = acc[mt][nt][i2*2+0] + __ldg(bias+cg);
                float v1 = acc[mt][nt][i2*2+1] + __ldg(bias+cg+1);
                v0 = gelu_exact(v0); v1 = gelu_exact(v1);
                size_t idx = (size_t)rg*DIMD + cg;
                if (EPI==1){
                    float2 xx = *(const float2*)(x+idx);
                    float2 mm = *(const float2*)(m1r+idx);
                    v0 *= xx.x*mm.x; v1 *= xx.y*mm.y;
                } else if (EPI==2){
                    float2 xx = *(const float2*)(x+idx);
                    v0 *= xx.x; v1 *= xx.y;
                }
                *(float2*)(Cout+idx) = make_float2(v0,v1);
            }
        }
    }
}

// ---------------------------------------------------------------- k_gram
// upper-triangle block-pairs; dual row/col max via dist symmetry
__global__ void __launch_bounds__(256) k_gram(){
    extern __shared__ float dsm[];
    uint32_t sA = smem_u32(dsm);
    uint32_t sB = sA + SB_OFF;
    __shared__ int   smax_i[128], smax_j[128];
    __shared__ float sqi_s[128], sqj_s[128];

    int tid = threadIdx.x, lane = tid&31;
    int wm = (tid>>5)&1, wn = tid>>6;
    int r = lane>>2, c = lane&3;
    int b = blockIdx.y;
    int tt = blockIdx.x, ib = 0;
    while (tt >= (8-ib)){ tt -= (8-ib); ib++; }
    int jb = ib + tt;

    if (tid<128){
        sqi_s[tid] = g_sq[b*NTOK + ib*128 + tid];
        sqj_s[tid] = g_sq[b*NTOK + jb*128 + tid];
        smax_i[tid]=0; smax_j[tid]=0;
    }

    float acc[4][4][4];
    #pragma unroll
    for (int a=0;a<4;a++)
      #pragma unroll
      for (int bb=0;bb<4;bb++)
        #pragma unroll
        for (int e=0;e<4;e++) acc[a][bb][e]=0.f;

    const int KT = DIMD/32;   // 24
    auto load_stage = [&](int kt){
        int st = kt % 3;
        uint32_t dA = sA + st*STG_A;
        uint32_t dB = sB + st*STG_B;
        int j0 = (kt*32)>>3;
        #pragma unroll
        for (int it=0; it<4; it++){
            int idx = it*256 + tid;
            int i = idx>>7, remA = idx&127;
            cpa16(dA + idx*16, g_Ap + ((size_t)(b*64+ib*8+i)*(DIMD>>3) + j0)*128 + remA*4);
            int nblk = idx>>6, remB = idx&63;
            cpa16(dB + idx*16, g_Ab + ((size_t)(b*128+jb*16+nblk)*(DIMD>>3) + j0)*64 + remB*4);
        }
        cpa_commit();
    };

    load_stage(0); load_stage(1);
    for (int kt=0; kt<KT; kt++){
        cpa_wait1();
        __syncthreads();
        if (kt+2 < KT) load_stage(kt+2); else cpa_commit();
        int st = kt % 3;
        uint32_t bA = sA + st*STG_A;
        uint32_t bB = sB + st*STG_B;
        #pragma unroll
        for (int jj=0;jj<4;jj++){
            float4 af[4]; float2 bf[4];
            #pragma unroll
            for (int mt=0;mt<4;mt++){
                uint32_t a = bA + ((((wm*4+mt)*4+jj))<<9) + (lane<<4);
                asm volatile("ld.shared.v4.f32 {%0,%1,%2,%3},[%4];"
                  : "=f"(af[mt].x),"=f"(af[mt].y),"=f"(af[mt].z),"=f"(af[mt].w) : "r"(a));
            }
            #pragma unroll
            for (int nt=0;nt<4;nt++){
                uint32_t a = bB + ((((wn*4+nt)*4+jj))<<8) + (lane<<3);
                asm volatile("ld.shared.v2.f32 {%0,%1},[%2];"
                  : "=f"(bf[nt].x),"=f"(bf[nt].y) : "r"(a));
            }
            #pragma unroll
            for (int mt=0;mt<4;mt++)
                #pragma unroll
                for (int nt=0;nt<4;nt++)
                    mma8(acc[mt][nt], &af[mt].x, &bf[nt].x);
        }
    }

    // epilogue: dist + dual max
    float rmax[8], cmax[8];
    #pragma unroll
    for (int i=0;i<8;i++){ rmax[i]=0.f; cmax[i]=0.f; }
    #pragma unroll
    for (int mt=0; mt<4; mt++){
        #pragma unroll
        for (int i2=0; i2<2; i2++){
            int rl = wm*64 + mt*16 + r + i2*8;
            float si = sqi_s[rl];
            #pragma unroll
            for (int nt=0; nt<4; nt++){
                #pragma unroll
                for (int q=0; q<2; q++){
                    int cl = wn*32 + nt*8 + 2*c + q;
                    float d2 = si + sqj_s[cl] - 2.f*acc[mt][nt][i2*2+q];
                    float dd = sqrtf(fmaxf(d2, 1e-12f));
                    rmax[mt*2+i2] = fmaxf(rmax[mt*2+i2], dd);
                    cmax[nt*2+q]  = fmaxf(cmax[nt*2+q],  dd);
                }
            }
        }
    }
    #pragma unroll
    for (int mt=0; mt<4; mt++)
        #pragma unroll
        for (int i2=0; i2<2; i2++)
            atomicMax(&smax_i[wm*64+mt*16+r+i2*8], __float_as_int(rmax[mt*2+i2]));
    #pragma unroll
    for (int nt=0; nt<4; nt++)
        #pragma unroll
        for (int q=0; q<2; q++)
            atomicMax(&smax_j[wn*32+nt*8+2*c+q], __float_as_int(cmax[nt*2+q]));
    __syncthreads();
    if (tid<128){
        atomicMax((int*)&g_m[b*NTOK + ib*128 + tid], smax_i[tid]);
        atomicMax((int*)&g_m[b*NTOK + jb*128 + tid], smax_j[tid]);
    }
}

// ---------------------------------------------------------------- launch
extern "C" void kernel_launch(void* const* d_in, const int* in_sizes, int n_in,
                              void* d_out, int out_size) {
    const float* x     = (const float*)d_in[0];
    const float* gamma = (const float*)d_in[1];
    const float* beta  = (const float*)d_in[2];
    const float* w1 = (const float*)d_in[3];
    const float* b1 = (const float*)d_in[4];
    const float* w2 = (const float*)d_in[5];
    const float* b2 = (const float*)d_in[6];
    const float* w3 = (const float*)d_in[7];
    const float* b3 = (const float*)d_in[8];
    const float* w4 = (const float*)d_in[9];
    const float* b4 = (const float*)d_in[10];
    float* out = (float*)d_out;

    cudaFuncSetAttribute(k_gram,       cudaFuncAttributeMaxDynamicSharedMemorySize, DSMEM_SZ);
    cudaFuncSetAttribute(k_gemm<2,0>,  cudaFuncAttributeMaxDynamicSharedMemorySize, DSMEM_SZ);
    cudaFuncSetAttribute(k_gemm<1,0>,  cudaFuncAttributeMaxDynamicSharedMemorySize, DSMEM_SZ);
    cudaFuncSetAttribute(k_gemm<1,1>,  cudaFuncAttributeMaxDynamicSharedMemorySize, DSMEM_SZ);
    cudaFuncSetAttribute(k_gemm<1,2>,  cudaFuncAttributeMaxDynamicSharedMemorySize, DSMEM_SZ);

    float *wB, *Ap, *rm0, *rm1;
    cudaGetSymbolAddress((void**)&wB,  g_wB);
    cudaGetSymbolAddress((void**)&Ap,  g_Ap);
    cudaGetSymbolAddress((void**)&rm0, g_rm0);
    cudaGetSymbolAddress((void**)&rm1, g_rm1);

    // weights -> B-format (tf32)
    k_tr<<<dim3(2*DIMD, 3), 256>>>(w1, wB+W1B, 2*DIMD);
    k_tr<<<dim3(DIMD,   3), 256>>>(w2, wB+W2B, DIMD);
    k_tr<<<dim3(DIMD,   3), 256>>>(w3, wB+W3B, DIMD);
    k_tr<<<dim3(DIMD,   3), 256>>>(w4, wB+W4B, DIMD);

    k_avg<<<NB*DIMD/256, 256>>>(x);
    k_ln <<<MTOT, 256>>>(x, gamma, beta);

    k_gram<<<dim3(36, NB), 256, DSMEM_SZ>>>();

    dim3 gg(DIMD/128, MTOT/128);
    // layer1: m1 = gelu([A | x+m] @ w1 + b1)                 -> g_rm0
    k_gemm<2,0><<<gg,256,DSMEM_SZ>>>(Ap,  wB+W1B, b1, x, nullptr, rm0, 2*DIMD);
    // layer2: t = x * m1 * gelu(m1 @ w2 + b2)                -> g_rm1
    k_gemm<1,1><<<gg,256,DSMEM_SZ>>>(rm0, wB+W2B, b2, x, rm0,     rm1, DIMD);
    // layer3: x*l3 = x * gelu(t @ w3 + b3)                   -> g_rm0
    k_gemm<1,2><<<gg,256,DSMEM_SZ>>>(rm1, wB+W3B, b3, x, nullptr, rm0, DIMD);
    // layer4: out = gelu((x*l3) @ w4 + b4)
    k_gemm<1,0><<<gg,256,DSMEM_SZ>>>(rm0, wB+W4B, b4, x, nullptr, out, DIMD);
}

// round 5
// speedup vs baseline: 1.7759x; 1.7759x over previous
#include <cuda_runtime.h>
#include <math.h>
#include <stdint.h>

#define DIMD 768
#define NTOK 1024
#define NB   16
#define MTOT (NB*NTOK)   // 16384

// ---------------- scratch (static device globals) --------------------------
__device__ float g_avg[NB*DIMD];
__device__ float g_sq [MTOT];
__device__ float g_m  [MTOT];
__device__ float g_cat[MTOT*2*DIMD];   // [A | tf32(x+m)] P-format, K=1536
__device__ float g_Ab [MTOT*DIMD];     // A in B-format (gram j-side)
__device__ float g_m1p[MTOT*DIMD];     // tf32(m1) P-format
__device__ float g_m1r[MTOT*DIMD];     // m1 raw row-major (gating)
__device__ float g_tp [MTOT*DIMD];     // tf32(t) P-format
__device__ float g_xlp[MTOT*DIMD];     // tf32(x*l3) P-format
__device__ float g_wB [5*DIMD*DIMD];   // weights B-format (tf32)
#define W1B 0
#define W2B (2*DIMD*DIMD)
#define W3B (3*DIMD*DIMD)
#define W4B (4*DIMD*DIMD)

// ---------------- helpers ---------------------------------------------------
__device__ __forceinline__ float tf32r(float x){
    unsigned u; asm("cvt.rna.tf32.f32 %0, %1;" : "=r"(u) : "f"(x));
    return __uint_as_float(u);
}
__device__ __forceinline__ float gelu_exact(float v){ return v * normcdff(v); }
__device__ __forceinline__ uint32_t smem_u32(const void* p){
    uint32_t a; asm("{ .reg .u64 t; cvta.to.shared.u64 t, %1; cvt.u32.u64 %0, t; }" : "=r"(a) : "l"(p));
    return a;
}
// P-format: per 16(row)x8(k) subtile: 32 lanes x float4 {A[r][k],A[r+8][k],A[r][k+4],A[r+8][k+4]}
__device__ __forceinline__ int addrP(int r, int k, int K){
    return ((r>>4)*(K>>3) + (k>>3))*128 + ((r&7)*4 + (k&3))*4 + ((r>>3)&1) + (((k>>2)&1)<<1);
}
// B-format: per 8(n)x8(k) subtile: 32 lanes x float2 {B[k][n],B[k+4][n]}
__device__ __forceinline__ int addrB(int n, int k, int K){
    return ((n>>3)*(K>>3) + (k>>3))*64 + ((n&7)*4 + (k&3))*2 + ((k>>2)&1);
}
__device__ __forceinline__ void cpa16(uint32_t dst, const float* src){
    asm volatile("cp.async.cg.shared.global [%0], [%1], 16;" :: "r"(dst), "l"(src));
}
__device__ __forceinline__ void cpa_commit(){ asm volatile("cp.async.commit_group;"); }
__device__ __forceinline__ void cpa_wait1(){ asm volatile("cp.async.wait_group 1;"); }

__device__ __forceinline__ void mma8(float* cc, const float* a, const float* b){
    asm volatile("mma.sync.aligned.m16n8k8.row.col.f32.tf32.tf32.f32 "
       "{%0,%1,%2,%3},{%4,%5,%6,%7},{%8,%9},{%0,%1,%2,%3};"
       : "+f"(cc[0]),"+f"(cc[1]),"+f"(cc[2]),"+f"(cc[3])
       : "r"(__float_as_uint(a[0])),"r"(__float_as_uint(a[1])),
         "r"(__float_as_uint(a[2])),"r"(__float_as_uint(a[3])),
         "r"(__float_as_uint(b[0])),"r"(__float_as_uint(b[1])));
}

#define STG_A 16384u
#define STG_B 16384u
#define SB_OFF 49152u
#define DSMEM_SZ 98304
#define XM_SMEM (16*772*4)

// ---------------------------------------------------------------- k_avg
__global__ void k_avg(const float* __restrict__ x){
    int gid = blockIdx.x*256 + threadIdx.x;
    int b = gid / DIMD, d = gid % DIMD;
    const float* p = x + (size_t)b*NTOK*DIMD + d;
    float s = 0.f;
    #pragma unroll 8
    for (int n = 0; n < NTOK; n++) s += p[n*DIMD];
    g_avg[gid] = s * (1.0f/NTOK);
}

// ---------------------------------------------------------------- k_ln
// A = tf32(avg*sigmoid(LN(x))) -> g_cat (P, K=1536, lower half), g_Ab (B-fmt)
__global__ void k_ln(const float* __restrict__ x,
                     const float* __restrict__ gamma,
                     const float* __restrict__ beta){
    int tok = blockIdx.x;
    int b = tok >> 10;
    const float* xp = x + (size_t)tok*DIMD;
    int t = threadIdx.x;
    float v[3]; float s=0.f, s2=0.f;
    #pragma unroll
    for (int i=0;i<3;i++){ v[i]=xp[t+256*i]; s+=v[i]; s2+=v[i]*v[i]; }
    __shared__ float red[16];
    #pragma unroll
    for (int o=16;o;o>>=1){ s+=__shfl_xor_sync(~0u,s,o); s2+=__shfl_xor_sync(~0u,s2,o); }
    int w = t>>5;
    if ((t&31)==0){ red[w]=s; red[w+8]=s2; }
    __syncthreads();
    if (t<32){
        float a=(t<8)?red[t]:0.f, bb=(t<8)?red[t+8]:0.f;
        #pragma unroll
        for (int o=4;o;o>>=1){ a+=__shfl_xor_sync(~0u,a,o); bb+=__shfl_xor_sync(~0u,bb,o); }
        if (t==0){ red[0]=a; red[1]=bb; }
    }
    __syncthreads();
    float mu  = red[0]*(1.f/DIMD);
    float var = red[1]*(1.f/DIMD) - mu*mu;
    float rs  = rsqrtf(var + 1e-5f);
    float asq = 0.f;
    const float* av = g_avg + b*DIMD;
    #pragma unroll
    for (int i=0;i<3;i++){
        int d = t + 256*i;
        float y  = (v[i]-mu)*rs*gamma[d] + beta[d];
        float sg = 1.f/(1.f+expf(-y));
        float a  = tf32r(av[d]*sg);
        g_cat[addrP(tok,d,2*DIMD)] = a;
        g_Ab [addrB(tok,d,DIMD)]  = a;
        asq += a*a;
    }
    #pragma unroll
    for (int o=16;o;o>>=1) asq += __shfl_xor_sync(~0u,asq,o);
    __syncthreads();
    if ((t&31)==0) red[w]=asq;
    __syncthreads();
    if (t==0){
        float a=0.f;
        #pragma unroll
        for (int i=0;i<8;i++) a+=red[i];
        g_sq[tok]=a;
        g_m[tok]=0.f;
    }
}

// ---------------------------------------------------------------- k_tr
__global__ void k_tr(const float* __restrict__ w, float* __restrict__ wB, int K){
    int n = blockIdx.y*256 + threadIdx.x;
    int k = blockIdx.x;
    wB[addrB(n,k,K)] = tf32r(w[(size_t)k*DIMD + n]);
}

// ---------------------------------------------------------------- k_xm
// upper half of g_cat: tf32(x+m) in P-format, coalesced via smem transpose
__global__ void __launch_bounds__(256) k_xm(const float* __restrict__ x){
    extern __shared__ float s[];   // 16 rows x 772
    int tb = blockIdx.x;           // 16-row block (0..1023)
    int tid = threadIdx.x;
    #pragma unroll
    for (int it=0; it<12; it++){
        int idx = it*256 + tid;    // float4 index, 0..3071
        int row = idx/192, c4 = idx%192;
        int tok = tb*16 + row;
        float4 v = *(const float4*)(x + (size_t)tok*DIMD + c4*4);
        float mm = g_m[tok];
        float* d = s + row*772 + c4*4;
        d[0]=tf32r(v.x+mm); d[1]=tf32r(v.y+mm); d[2]=tf32r(v.z+mm); d[3]=tf32r(v.w+mm);
    }
    __syncthreads();
    int w = tid>>5, l = tid&31;
    int r7 = l>>2, k3 = l&3;
    #pragma unroll
    for (int it=0; it<12; it++){
        int kb = it*8 + w;         // 0..95
        int kk = kb*8 + k3;
        float4 o;
        o.x = s[ r7   *772 + kk];
        o.y = s[(r7+8)*772 + kk];
        o.z = s[ r7   *772 + kk+4];
        o.w = s[(r7+8)*772 + kk+4];
        *(float4*)(g_cat + ((size_t)tb*192 + 96 + kb)*128 + l*4) = o;
    }
}

// ---------------------------------------------------------------- k_gemm
// All operands pre-permuted in global; pure cp.async both sides.
// EPI 0: gelu   1: gelu*x*m1r   2: gelu*x
// OUT 0: Cp=tf32(P) + Cr=raw row   1: Cp=tf32(P)   2: Cr=raw row
template<int EPI, int OUT>
__global__ void __launch_bounds__(256) k_gemm(
    const float* __restrict__ pA, const float* __restrict__ pB,
    const float* __restrict__ bias, const float* __restrict__ x,
    const float* __restrict__ m1r, float* __restrict__ Cp,
    float* __restrict__ Cr, int Ktot)
{
    extern __shared__ float dsm[];
    uint32_t sA = smem_u32(dsm);
    uint32_t sB = sA + SB_OFF;
    int tid = threadIdx.x, lane = tid&31;
    int wm = (tid>>5)&1, wn = tid>>6;
    int r = lane>>2, c = lane&3;
    int nb = blockIdx.x, mb = blockIdx.y;
    const int KT = Ktot/32;
    const int KB = Ktot>>3;

    float acc[4][4][4];
    #pragma unroll
    for (int a=0;a<4;a++)
      #pragma unroll
      for (int b=0;b<4;b++)
        #pragma unroll
        for (int e=0;e<4;e++) acc[a][b][e]=0.f;

    auto load_stage = [&](int kt){
        int st = kt % 3;
        uint32_t dA = sA + st*STG_A;
        uint32_t dB = sB + st*STG_B;
        int j0 = kt*4;
        #pragma unroll
        for (int it=0; it<4; it++){
            int idx = it*256 + tid;
            int i = idx>>7, remA = idx&127;
            cpa16(dA + idx*16, pA + ((size_t)(mb*8+i)*KB + j0)*128 + remA*4);
            int nblk = idx>>6, remB = idx&63;
            cpa16(dB + idx*16, pB + ((size_t)(nb*16+nblk)*KB + j0)*64 + remB*4);
        }
        cpa_commit();
    };

    load_stage(0); load_stage(1);
    for (int kt=0; kt<KT; kt++){
        cpa_wait1();
        __syncthreads();
        if (kt+2 < KT) load_stage(kt+2); else cpa_commit();
        int st = kt % 3;
        uint32_t bA = sA + st*STG_A;
        uint32_t bB = sB + st*STG_B;
        #pragma unroll
        for (int jj=0;jj<4;jj++){
            float4 af[4]; float2 bf[4];
            #pragma unroll
            for (int mt=0;mt<4;mt++){
                uint32_t a = bA + ((((wm*4+mt)*4+jj))<<9) + (lane<<4);
                asm volatile("ld.shared.v4.f32 {%0,%1,%2,%3},[%4];"
                  : "=f"(af[mt].x),"=f"(af[mt].y),"=f"(af[mt].z),"=f"(af[mt].w) : "r"(a));
            }
            #pragma unroll
            for (int nt=0;nt<4;nt++){
                uint32_t a = bB + ((((wn*4+nt)*4+jj))<<8) + (lane<<3);
                asm volatile("ld.shared.v2.f32 {%0,%1},[%2];"
                  : "=f"(bf[nt].x),"=f"(bf[nt].y) : "r"(a));
            }
            #pragma unroll
            for (int mt=0;mt<4;mt++)
                #pragma unroll
                for (int nt=0;nt<4;nt++)
                    mma8(acc[mt][nt], &af[mt].x, &bf[nt].x);
        }
    }

    // epilogue
    #pragma unroll
    for (int mt=0; mt<4; mt++){
        int rp = mb*128 + wm*64 + mt*16 + r;     // (rp>>3)&1 == 0
        #pragma unroll
        for (int nt=0; nt<4; nt++){
            int cg = nb*128 + wn*32 + nt*8 + 2*c;
            float bb0 = __ldg(bias+cg), bb1 = __ldg(bias+cg+1);
            float a0 = gelu_exact(acc[mt][nt][0] + bb0);
            float a1 = gelu_exact(acc[mt][nt][1] + bb1);
            float a2 = gelu_exact(acc[mt][nt][2] + bb0);
            float a3 = gelu_exact(acc[mt][nt][3] + bb1);
            size_t i0 = (size_t)rp*DIMD + cg, i1 = (size_t)(rp+8)*DIMD + cg;
            if (EPI==1){
                float2 xa=*(const float2*)(x+i0),  xb=*(const float2*)(x+i1);
                float2 ma=*(const float2*)(m1r+i0), mz=*(const float2*)(m1r+i1);
                a0*=xa.x*ma.x; a1*=xa.y*ma.y; a2*=xb.x*mz.x; a3*=xb.y*mz.y;
            } else if (EPI==2){
                float2 xa=*(const float2*)(x+i0), xb=*(const float2*)(x+i1);
                a0*=xa.x; a1*=xa.y; a2*=xb.x; a3*=xb.y;
            }
            if (OUT==0 || OUT==2){
                *(float2*)(Cr+i0) = make_float2(a0,a1);
                *(float2*)(Cr+i1) = make_float2(a2,a3);
            }
            if (OUT<=1){
                *(float2*)(Cp + addrP(rp, cg,   DIMD)) = make_float2(tf32r(a0), tf32r(a2));
                *(float2*)(Cp + addrP(rp, cg+1, DIMD)) = make_float2(tf32r(a1), tf32r(a3));
            }
        }
    }
}

// ---------------------------------------------------------------- k_gram
// upper-triangle block-pairs; dual row/col max via symmetry
__global__ void __launch_bounds__(256) k_gram(){
    extern __shared__ float dsm[];
    uint32_t sA = smem_u32(dsm);
    uint32_t sB = sA + SB_OFF;
    __shared__ int   smax_i[128], smax_j[128];
    __shared__ float sqi_s[128], sqj_s[128];

    int tid = threadIdx.x, lane = tid&31;
    int wm = (tid>>5)&1, wn = tid>>6;
    int r = lane>>2, c = lane&3;
    int b = blockIdx.y;
    int tt = blockIdx.x, ib = 0;
    while (tt >= (8-ib)){ tt -= (8-ib); ib++; }
    int jb = ib + tt;

    if (tid<128){
        sqi_s[tid] = g_sq[b*NTOK + ib*128 + tid];
        sqj_s[tid] = g_sq[b*NTOK + jb*128 + tid];
        smax_i[tid]=0; smax_j[tid]=0;
    }

    float acc[4][4][4];
    #pragma unroll
    for (int a=0;a<4;a++)
      #pragma unroll
      for (int bb=0;bb<4;bb++)
        #pragma unroll
        for (int e=0;e<4;e++) acc[a][bb][e]=0.f;

    const int KT = DIMD/32;   // 24
    auto load_stage = [&](int kt){
        int st = kt % 3;
        uint32_t dA = sA + st*STG_A;
        uint32_t dB = sB + st*STG_B;
        int j0 = kt*4;
        #pragma unroll
        for (int it=0; it<4; it++){
            int idx = it*256 + tid;
            int i = idx>>7, remA = idx&127;
            cpa16(dA + idx*16, g_cat + ((size_t)(b*64+ib*8+i)*192 + j0)*128 + remA*4);
            int nblk = idx>>6, remB = idx&63;
            cpa16(dB + idx*16, g_Ab + ((size_t)(b*128+jb*16+nblk)*96 + j0)*64 + remB*4);
        }
        cpa_commit();
    };

    load_stage(0); load_stage(1);
    for (int kt=0; kt<KT; kt++){
        cpa_wait1();
        __syncthreads();
        if (kt+2 < KT) load_stage(kt+2); else cpa_commit();
        int st = kt % 3;
        uint32_t bA = sA + st*STG_A;
        uint32_t bB = sB + st*STG_B;
        #pragma unroll
        for (int jj=0;jj<4;jj++){
            float4 af[4]; float2 bf[4];
            #pragma unroll
            for (int mt=0;mt<4;mt++){
                uint32_t a = bA + ((((wm*4+mt)*4+jj))<<9) + (lane<<4);
                asm volatile("ld.shared.v4.f32 {%0,%1,%2,%3},[%4];"
                  : "=f"(af[mt].x),"=f"(af[mt].y),"=f"(af[mt].z),"=f"(af[mt].w) : "r"(a));
            }
            #pragma unroll
            for (int nt=0;nt<4;nt++){
                uint32_t a = bB + ((((wn*4+nt)*4+jj))<<8) + (lane<<3);
                asm volatile("ld.shared.v2.f32 {%0,%1},[%2];"
                  : "=f"(bf[nt].x),"=f"(bf[nt].y) : "r"(a));
            }
            #pragma unroll
            for (int mt=0;mt<4;mt++)
                #pragma unroll
                for (int nt=0;nt<4;nt++)
                    mma8(acc[mt][nt], &af[mt].x, &bf[nt].x);
        }
    }

    float rmax[8], cmax[8];
    #pragma unroll
    for (int i=0;i<8;i++){ rmax[i]=0.f; cmax[i]=0.f; }
    #pragma unroll
    for (int mt=0; mt<4; mt++){
        #pragma unroll
        for (int i2=0; i2<2; i2++){
            int rl = wm*64 + mt*16 + r + i2*8;
            float si = sqi_s[rl];
            #pragma unroll
            for (int nt=0; nt<4; nt++){
                #pragma unroll
                for (int q=0; q<2; q++){
                    int cl = wn*32 + nt*8 + 2*c + q;
                    float d2 = si + sqj_s[cl] - 2.f*acc[mt][nt][i2*2+q];
                    float dd = sqrtf(fmaxf(d2, 1e-12f));
                    rmax[mt*2+i2] = fmaxf(rmax[mt*2+i2], dd);
                    cmax[nt*2+q]  = fmaxf(cmax[nt*2+q],  dd);
                }
            }
        }
    }
    #pragma unroll
    for (int mt=0; mt<4; mt++)
        #pragma unroll
        for (int i2=0; i2<2; i2++)
            atomicMax(&smax_i[wm*64+mt*16+r+i2*8], __float_as_int(rmax[mt*2+i2]));
    #pragma unroll
    for (int nt=0; nt<4; nt++)
        #pragma unroll
        for (int q=0; q<2; q++)
            atomicMax(&smax_j[wn*32+nt*8+2*c+q], __float_as_int(cmax[nt*2+q]));
    __syncthreads();
    if (tid<128){
        atomicMax((int*)&g_m[b*NTOK + ib*128 + tid], smax_i[tid]);
        atomicMax((int*)&g_m[b*NTOK + jb*128 + tid], smax_j[tid]);
    }
}

// ---------------------------------------------------------------- launch
extern "C" void kernel_launch(void* const* d_in, const int* in_sizes, int n_in,
                              void* d_out, int out_size) {
    const float* x     = (const float*)d_in[0];
    const float* gamma = (const float*)d_in[1];
    const float* beta  = (const float*)d_in[2];
    const float* w1 = (const float*)d_in[3];
    const float* b1 = (const float*)d_in[4];
    const float* w2 = (const float*)d_in[5];
    const float* b2 = (const float*)d_in[6];
    const float* w3 = (const float*)d_in[7];
    const float* b3 = (const float*)d_in[8];
    const float* w4 = (const float*)d_in[9];
    const float* b4 = (const float*)d_in[10];
    float* out = (float*)d_out;

    cudaFuncSetAttribute(k_gram,      cudaFuncAttributeMaxDynamicSharedMemorySize, DSMEM_SZ);
    cudaFuncSetAttribute(k_xm,        cudaFuncAttributeMaxDynamicSharedMemorySize, XM_SMEM);
    cudaFuncSetAttribute(k_gemm<0,0>, cudaFuncAttributeMaxDynamicSharedMemorySize, DSMEM_SZ);
    cudaFuncSetAttribute(k_gemm<1,1>, cudaFuncAttributeMaxDynamicSharedMemorySize, DSMEM_SZ);
    cudaFuncSetAttribute(k_gemm<2,1>, cudaFuncAttributeMaxDynamicSharedMemorySize, DSMEM_SZ);
    cudaFuncSetAttribute(k_gemm<0,2>, cudaFuncAttributeMaxDynamicSharedMemorySize, DSMEM_SZ);

    float *wB, *cat, *m1p, *m1r, *tp, *xlp;
    cudaGetSymbolAddress((void**)&wB,  g_wB);
    cudaGetSymbolAddress((void**)&cat, g_cat);
    cudaGetSymbolAddress((void**)&m1p, g_m1p);
    cudaGetSymbolAddress((void**)&m1r, g_m1r);
    cudaGetSymbolAddress((void**)&tp,  g_tp);
    cudaGetSymbolAddress((void**)&xlp, g_xlp);

    k_tr<<<dim3(2*DIMD, 3), 256>>>(w1, wB+W1B, 2*DIMD);
    k_tr<<<dim3(DIMD,   3), 256>>>(w2, wB+W2B, DIMD);
    k_tr<<<dim3(DIMD,   3), 256>>>(w3, wB+W3B, DIMD);
    k_tr<<<dim3(DIMD,   3), 256>>>(w4, wB+W4B, DIMD);

    k_avg<<<NB*DIMD/256, 256>>>(x);
    k_ln <<<MTOT, 256>>>(x, gamma, beta);

    k_gram<<<dim3(36, NB), 256, DSMEM_SZ>>>();
    k_xm  <<<MTOT/16, 256, XM_SMEM>>>(x);

    dim3 gg(DIMD/128, MTOT/128);
    // layer1: m1 = gelu(cat @ w1 + b1)            -> m1p (tf32 P) + m1r (raw)
    k_gemm<0,0><<<gg,256,DSMEM_SZ>>>(cat, wB+W1B, b1, x, nullptr, m1p, m1r, 2*DIMD);
    // layer2: t = x*m1*gelu(m1 @ w2 + b2)         -> tp (tf32 P)
    k_gemm<1,1><<<gg,256,DSMEM_SZ>>>(m1p, wB+W2B, b2, x, m1r,     tp,  nullptr, DIMD);
    // layer3: x*l3 = x*gelu(t @ w3 + b3)          -> xlp (tf32 P)
    k_gemm<2,1><<<gg,256,DSMEM_SZ>>>(tp,  wB+W3B, b3, x, nullptr, xlp, nullptr, DIMD);
    // layer4: out = gelu((x*l3) @ w4 + b4)        -> out (row)
    k_gemm<0,2><<<gg,256,DSMEM_SZ>>>(xlp, wB+W4B, b4, x, nullptr, nullptr, out, DIMD);
}

// round 6
// speedup vs baseline: 1.8687x; 1.0522x over previous
#include <cuda_runtime.h>
#include <math.h>
#include <stdint.h>

#define DIMD 768
#define NTOK 1024
#define NB   16
#define MTOT (NB*NTOK)   // 16384

// ---------------- scratch (static device globals) --------------------------
__device__ float g_avg[NB*DIMD];
__device__ float g_pav[8*NB*DIMD];     // partial sums for k_avg
__device__ float g_sq [MTOT];
__device__ float g_m  [MTOT];
__device__ float g_cat[MTOT*2*DIMD];   // [A | tf32(x+m)] P-format, K=1536
__device__ float g_Ab [MTOT*DIMD];     // A in B-format (gram j-side)
__device__ float g_m1p[MTOT*DIMD];     // tf32(m1) P-format
__device__ float g_m1r[MTOT*DIMD];     // m1 raw row-major (gating)
__device__ float g_tp [MTOT*DIMD];     // tf32(t) P-format
__device__ float g_xlp[MTOT*DIMD];     // tf32(x*l3) P-format
__device__ float g_wB [5*DIMD*DIMD];   // weights B-format (tf32)
#define W1B 0
#define W2B (2*DIMD*DIMD)
#define W3B (3*DIMD*DIMD)
#define W4B (4*DIMD*DIMD)

// ---------------- helpers ---------------------------------------------------
__device__ __forceinline__ float tf32r(float x){
    unsigned u; asm("cvt.rna.tf32.f32 %0, %1;" : "=r"(u) : "f"(x));
    return __uint_as_float(u);
}
__device__ __forceinline__ float gelu_exact(float v){ return v * normcdff(v); }
__device__ __forceinline__ uint32_t smem_u32(const void* p){
    uint32_t a; asm("{ .reg .u64 t; cvta.to.shared.u64 t, %1; cvt.u32.u64 %0, t; }" : "=r"(a) : "l"(p));
    return a;
}
// P-format: per 16(row)x8(k) subtile: 32 lanes x float4 {A[r][k],A[r+8][k],A[r][k+4],A[r+8][k+4]}
__device__ __forceinline__ int addrP(int r, int k, int K){
    return ((r>>4)*(K>>3) + (k>>3))*128 + ((r&7)*4 + (k&3))*4 + ((r>>3)&1) + (((k>>2)&1)<<1);
}
// B-format: per 8(n)x8(k) subtile: 32 lanes x float2 {B[k][n],B[k+4][n]}
__device__ __forceinline__ int addrB(int n, int k, int K){
    return ((n>>3)*(K>>3) + (k>>3))*64 + ((n&7)*4 + (k&3))*2 + ((k>>2)&1);
}
__device__ __forceinline__ void cpa16(uint32_t dst, const float* src){
    asm volatile("cp.async.cg.shared.global [%0], [%1], 16;" :: "r"(dst), "l"(src));
}
__device__ __forceinline__ void cpa_commit(){ asm volatile("cp.async.commit_group;"); }
__device__ __forceinline__ void cpa_wait1(){ asm volatile("cp.async.wait_group 1;"); }

__device__ __forceinline__ void mma8(float* cc, const float* a, const float* b){
    asm volatile("mma.sync.aligned.m16n8k8.row.col.f32.tf32.tf32.f32 "
       "{%0,%1,%2,%3},{%4,%5,%6,%7},{%8,%9},{%0,%1,%2,%3};"
       : "+f"(cc[0]),"+f"(cc[1]),"+f"(cc[2]),"+f"(cc[3])
       : "r"(__float_as_uint(a[0])),"r"(__float_as_uint(a[1])),
         "r"(__float_as_uint(a[2])),"r"(__float_as_uint(a[3])),
         "r"(__float_as_uint(b[0])),"r"(__float_as_uint(b[1])));
}

#define STG_A 16384u
#define STG_B 16384u
#define SB_OFF 49152u
#define DSMEM_SZ 98304
#define LN_SMEM (16*772*4)

// ---------------------------------------------------------------- k_avg (2 phases)
__global__ void k_avg1(const float* __restrict__ x){
    int chunk = blockIdx.x, b = blockIdx.y;   // 8 x 16
    int t = threadIdx.x;                       // 192 (float4 over 768)
    const float4* p = (const float4*)(x + ((size_t)b*NTOK + chunk*128)*DIMD) + t;
    float4 s = make_float4(0.f,0.f,0.f,0.f);
    #pragma unroll 4
    for (int i=0;i<128;i++){
        float4 v = p[i*(DIMD/4)];
        s.x+=v.x; s.y+=v.y; s.z+=v.z; s.w+=v.w;
    }
    *((float4*)(g_pav + ((size_t)chunk*NB + b)*DIMD) + t) = s;
}
__global__ void k_avg2(){
    int gid = blockIdx.x*256 + threadIdx.x;    // 0..12287
    int b = gid / DIMD, d = gid % DIMD;
    float s = 0.f;
    #pragma unroll
    for (int c=0;c<8;c++) s += g_pav[((size_t)c*NB + b)*DIMD + d];
    g_avg[gid] = s * (1.0f/NTOK);
}

// ---------------------------------------------------------------- k_ln
// 16 tokens/block; A = tf32(avg*sigmoid(LN(x))) -> g_cat (P, lower K) + g_Ab (B-fmt)
__global__ void __launch_bounds__(256) k_ln(const float* __restrict__ x,
                                            const float* __restrict__ gamma,
                                            const float* __restrict__ beta){
    extern __shared__ float s[];               // 16 x 772
    int tb = blockIdx.x;                        // 0..1023
    int tid = threadIdx.x, w = tid>>5, l = tid&31;
    #pragma unroll
    for (int half=0; half<2; half++){
        int trow = w*2 + half;
        int tok  = tb*16 + trow;
        const float* xp = x + (size_t)tok*DIMD;
        float v[24]; float s1=0.f, s2=0.f;
        #pragma unroll
        for (int i=0;i<24;i++){ v[i]=xp[l+32*i]; s1+=v[i]; s2+=v[i]*v[i]; }
        #pragma unroll
        for (int o=16;o;o>>=1){ s1+=__shfl_xor_sync(~0u,s1,o); s2+=__shfl_xor_sync(~0u,s2,o); }
        float mu  = s1*(1.f/DIMD);
        float var = s2*(1.f/DIMD) - mu*mu;
        float rs  = rsqrtf(var + 1e-5f);
        const float* av = g_avg + (tok>>10)*DIMD;
        float asq = 0.f;
        #pragma unroll
        for (int i=0;i<24;i++){
            int d = l + 32*i;
            float y  = (v[i]-mu)*rs*gamma[d] + beta[d];
            float sg = 1.f/(1.f+expf(-y));
            float a  = tf32r(av[d]*sg);
            s[trow*772 + d] = a;
            asq += a*a;
        }
        #pragma unroll
        for (int o=16;o;o>>=1) asq += __shfl_xor_sync(~0u,asq,o);
        if (l==0){ g_sq[tok]=asq; g_m[tok]=0.f; }
    }
    __syncthreads();
    int r7 = l>>2, k3 = l&3;
    // P-format store into g_cat lower half (kb 0..95), coalesced float4
    #pragma unroll
    for (int it=0; it<12; it++){
        int kb = it*8 + w;
        int kk = kb*8 + k3;
        float4 o;
        o.x = s[ r7   *772 + kk];
        o.y = s[(r7+8)*772 + kk];
        o.z = s[ r7   *772 + kk+4];
        o.w = s[(r7+8)*772 + kk+4];
        *(float4*)(g_cat + ((size_t)tb*192 + kb)*128 + l*4) = o;
    }
    // B-format store into g_Ab, coalesced float2 (2 n-blocks x 96 k-blocks)
    #pragma unroll
    for (int it=0; it<24; it++){
        int sub = it*8 + w;              // 0..191
        int ng  = sub/96, kb = sub - ng*96;
        int n = ng*8 + r7, k = kb*8 + k3;
        float2 o; o.x = s[n*772 + k]; o.y = s[n*772 + k + 4];
        *(float2*)(g_Ab + (((size_t)(tb*2+ng))*96 + kb)*64 + 2*l) = o;
    }
}

// ---------------------------------------------------------------- k_xm
// upper half of g_cat: tf32(x+m) P-format; ALSO folds w1 -> B-format transpose
__global__ void __launch_bounds__(256) k_xm(const float* __restrict__ x,
                                            const float* __restrict__ w1){
    extern __shared__ float s[];   // 16 x 772
    int tb = blockIdx.x;           // 0..1023
    int tid = threadIdx.x;
    #pragma unroll
    for (int it=0; it<12; it++){
        int idx = it*256 + tid;
        int row = idx/192, c4 = idx%192;
        int tok = tb*16 + row;
        float4 v = *(const float4*)(x + (size_t)tok*DIMD + c4*4);
        float mm = g_m[tok];
        float* d = s + row*772 + c4*4;
        d[0]=tf32r(v.x+mm); d[1]=tf32r(v.y+mm); d[2]=tf32r(v.z+mm); d[3]=tf32r(v.w+mm);
    }
    __syncthreads();
    int w = tid>>5, l = tid&31;
    int r7 = l>>2, k3 = l&3;
    #pragma unroll
    for (int it=0; it<12; it++){
        int kb = it*8 + w;
        int kk = kb*8 + k3;
        float4 o;
        o.x = s[ r7   *772 + kk];
        o.y = s[(r7+8)*772 + kk];
        o.z = s[ r7   *772 + kk+4];
        o.w = s[(r7+8)*772 + kk+4];
        *(float4*)(g_cat + ((size_t)tb*192 + 96 + kb)*128 + l*4) = o;
    }
    // folded w1 transpose: 1152 elements per block
    #pragma unroll
    for (int it=0; it<4; it++){
        size_t idx = (size_t)tb*1152 + it*256 + tid;
        int k = (int)(idx/DIMD), n = (int)(idx%DIMD);
        g_wB[W1B + addrB(n,k,2*DIMD)] = tf32r(w1[idx]);
    }
    if (tid < 128){
        size_t idx = (size_t)tb*1152 + 1024 + tid;
        int k = (int)(idx/DIMD), n = (int)(idx%DIMD);
        g_wB[W1B + addrB(n,k,2*DIMD)] = tf32r(w1[idx]);
    }
}

// ---------------------------------------------------------------- k_tr_rest (w2..w4)
__global__ void k_tr_rest(const float* __restrict__ w2,
                          const float* __restrict__ w3,
                          const float* __restrict__ w4){
    int z = blockIdx.z;                          // 0..2
    int k = blockIdx.x;
    int n = blockIdx.y*256 + threadIdx.x;
    const float* w = (z==0)? w2 : (z==1)? w3 : w4;
    float* dst = g_wB + ((z==0)? W2B : (z==1)? W3B : W4B);
    dst[addrB(n,k,DIMD)] = tf32r(w[(size_t)k*DIMD + n]);
}

// ---------------------------------------------------------------- k_gemm
// EPI 0: gelu   1: gelu*x*m1r   2: gelu*x
// OUT 0: Cp=tf32(P) + Cr=raw row   1: Cp=tf32(P)   2: Cr=raw row
template<int EPI, int OUT>
__global__ void __launch_bounds__(256) k_gemm(
    const float* __restrict__ pA, const float* __restrict__ pB,
    const float* __restrict__ bias, const float* __restrict__ x,
    const float* __restrict__ m1r, float* __restrict__ Cp,
    float* __restrict__ Cr, int Ktot)
{
    extern __shared__ float dsm[];
    uint32_t sA = smem_u32(dsm);
    uint32_t sB = sA + SB_OFF;
    int tid = threadIdx.x, lane = tid&31;
    int wm = (tid>>5)&1, wn = tid>>6;
    int r = lane>>2, c = lane&3;
    int nb = blockIdx.x, mb = blockIdx.y;
    const int KT = Ktot/32;
    const int KB = Ktot>>3;

    float acc[4][4][4];
    #pragma unroll
    for (int a=0;a<4;a++)
      #pragma unroll
      for (int b=0;b<4;b++)
        #pragma unroll
        for (int e=0;e<4;e++) acc[a][b][e]=0.f;

    auto load_stage = [&](int kt){
        int st = kt % 3;
        uint32_t dA = sA + st*STG_A;
        uint32_t dB = sB + st*STG_B;
        int j0 = kt*4;
        #pragma unroll
        for (int it=0; it<4; it++){
            int idx = it*256 + tid;
            int i = idx>>7, remA = idx&127;
            cpa16(dA + idx*16, pA + ((size_t)(mb*8+i)*KB + j0)*128 + remA*4);
            int nblk = idx>>6, remB = idx&63;
            cpa16(dB + idx*16, pB + ((size_t)(nb*16+nblk)*KB + j0)*64 + remB*4);
        }
        cpa_commit();
    };

    load_stage(0); load_stage(1);
    for (int kt=0; kt<KT; kt++){
        cpa_wait1();
        __syncthreads();
        if (kt+2 < KT) load_stage(kt+2); else cpa_commit();
        int st = kt % 3;
        uint32_t bA = sA + st*STG_A;
        uint32_t bB = sB + st*STG_B;
        #pragma unroll
        for (int jj=0;jj<4;jj++){
            float4 af[4]; float2 bf[4];
            #pragma unroll
            for (int mt=0;mt<4;mt++){
                uint32_t a = bA + ((((wm*4+mt)*4+jj))<<9) + (lane<<4);
                asm volatile("ld.shared.v4.f32 {%0,%1,%2,%3},[%4];"
                  : "=f"(af[mt].x),"=f"(af[mt].y),"=f"(af[mt].z),"=f"(af[mt].w) : "r"(a));
            }
            #pragma unroll
            for (int nt=0;nt<4;nt++){
                uint32_t a = bB + ((((wn*4+nt)*4+jj))<<8) + (lane<<3);
                asm volatile("ld.shared.v2.f32 {%0,%1},[%2];"
                  : "=f"(bf[nt].x),"=f"(bf[nt].y) : "r"(a));
            }
            #pragma unroll
            for (int mt=0;mt<4;mt++)
                #pragma unroll
                for (int nt=0;nt<4;nt++)
                    mma8(acc[mt][nt], &af[mt].x, &bf[nt].x);
        }
    }

    // epilogue
    #pragma unroll
    for (int mt=0; mt<4; mt++){
        int rp = mb*128 + wm*64 + mt*16 + r;     // (rp>>3)&1 == 0
        #pragma unroll
        for (int nt=0; nt<4; nt++){
            int cg = nb*128 + wn*32 + nt*8 + 2*c;
            float bb0 = __ldg(bias+cg), bb1 = __ldg(bias+cg+1);
            float a0 = gelu_exact(acc[mt][nt][0] + bb0);
            float a1 = gelu_exact(acc[mt][nt][1] + bb1);
            float a2 = gelu_exact(acc[mt][nt][2] + bb0);
            float a3 = gelu_exact(acc[mt][nt][3] + bb1);
            size_t i0 = (size_t)rp*DIMD + cg, i1 = (size_t)(rp+8)*DIMD + cg;
            if (EPI==1){
                float2 xa=*(const float2*)(x+i0),  xb=*(const float2*)(x+i1);
                float2 ma=*(const float2*)(m1r+i0), mz=*(const float2*)(m1r+i1);
                a0*=xa.x*ma.x; a1*=xa.y*ma.y; a2*=xb.x*mz.x; a3*=xb.y*mz.y;
            } else if (EPI==2){
                float2 xa=*(const float2*)(x+i0), xb=*(const float2*)(x+i1);
                a0*=xa.x; a1*=xa.y; a2*=xb.x; a3*=xb.y;
            }
            if (OUT==0 || OUT==2){
                *(float2*)(Cr+i0) = make_float2(a0,a1);
                *(float2*)(Cr+i1) = make_float2(a2,a3);
            }
            if (OUT<=1){
                *(float2*)(Cp + addrP(rp, cg,   DIMD)) = make_float2(tf32r(a0), tf32r(a2));
                *(float2*)(Cp + addrP(rp, cg+1, DIMD)) = make_float2(tf32r(a1), tf32r(a3));
            }
        }
    }
}

// ---------------------------------------------------------------- k_gram
__global__ void __launch_bounds__(256) k_gram(){
    extern __shared__ float dsm[];
    uint32_t sA = smem_u32(dsm);
    uint32_t sB = sA + SB_OFF;
    __shared__ int   smax_i[128], smax_j[128];
    __shared__ float sqi_s[128], sqj_s[128];

    int tid = threadIdx.x, lane = tid&31;
    int wm = (tid>>5)&1, wn = tid>>6;
    int r = lane>>2, c = lane&3;
    int b = blockIdx.y;
    int tt = blockIdx.x, ib = 0;
    while (tt >= (8-ib)){ tt -= (8-ib); ib++; }
    int jb = ib + tt;

    if (tid<128){
        sqi_s[tid] = g_sq[b*NTOK + ib*128 + tid];
        sqj_s[tid] = g_sq[b*NTOK + jb*128 + tid];
        smax_i[tid]=0; smax_j[tid]=0;
    }

    float acc[4][4][4];
    #pragma unroll
    for (int a=0;a<4;a++)
      #pragma unroll
      for (int bb=0;bb<4;bb++)
        #pragma unroll
        for (int e=0;e<4;e++) acc[a][bb][e]=0.f;

    const int KT = DIMD/32;   // 24
    auto load_stage = [&](int kt){
        int st = kt % 3;
        uint32_t dA = sA + st*STG_A;
        uint32_t dB = sB + st*STG_B;
        int j0 = kt*4;
        #pragma unroll
        for (int it=0; it<4; it++){
            int idx = it*256 + tid;
            int i = idx>>7, remA = idx&127;
            cpa16(dA + idx*16, g_cat + ((size_t)(b*64+ib*8+i)*192 + j0)*128 + remA*4);
            int nblk = idx>>6, remB = idx&63;
            cpa16(dB + idx*16, g_Ab + ((size_t)(b*128+jb*16+nblk)*96 + j0)*64 + remB*4);
        }
        cpa_commit();
    };

    load_stage(0); load_stage(1);
    for (int kt=0; kt<KT; kt++){
        cpa_wait1();
        __syncthreads();
        if (kt+2 < KT) load_stage(kt+2); else cpa_commit();
        int st = kt % 3;
        uint32_t bA = sA + st*STG_A;
        uint32_t bB = sB + st*STG_B;
        #pragma unroll
        for (int jj=0;jj<4;jj++){
            float4 af[4]; float2 bf[4];
            #pragma unroll
            for (int mt=0;mt<4;mt++){
                uint32_t a = bA + ((((wm*4+mt)*4+jj))<<9) + (lane<<4);
                asm volatile("ld.shared.v4.f32 {%0,%1,%2,%3},[%4];"
                  : "=f"(af[mt].x),"=f"(af[mt].y),"=f"(af[mt].z),"=f"(af[mt].w) : "r"(a));
            }
            #pragma unroll
            for (int nt=0;nt<4;nt++){
                uint32_t a = bB + ((((wn*4+nt)*4+jj))<<8) + (lane<<3);
                asm volatile("ld.shared.v2.f32 {%0,%1},[%2];"
                  : "=f"(bf[nt].x),"=f"(bf[nt].y) : "r"(a));
            }
            #pragma unroll
            for (int mt=0;mt<4;mt++)
                #pragma unroll
                for (int nt=0;nt<4;nt++)
                    mma8(acc[mt][nt], &af[mt].x, &bf[nt].x);
        }
    }

    float rmax[8], cmax[8];
    #pragma unroll
    for (int i=0;i<8;i++){ rmax[i]=0.f; cmax[i]=0.f; }
    #pragma unroll
    for (int mt=0; mt<4; mt++){
        #pragma unroll
        for (int i2=0; i2<2; i2++){
            int rl = wm*64 + mt*16 + r + i2*8;
            float si = sqi_s[rl];
            #pragma unroll
            for (int nt=0; nt<4; nt++){
                #pragma unroll
                for (int q=0; q<2; q++){
                    int cl = wn*32 + nt*8 + 2*c + q;
                    float d2 = si + sqj_s[cl] - 2.f*acc[mt][nt][i2*2+q];
                    float dd = sqrtf(fmaxf(d2, 1e-12f));
                    rmax[mt*2+i2] = fmaxf(rmax[mt*2+i2], dd);
                    cmax[nt*2+q]  = fmaxf(cmax[nt*2+q],  dd);
                }
            }
        }
    }
    #pragma unroll
    for (int mt=0; mt<4; mt++)
        #pragma unroll
        for (int i2=0; i2<2; i2++)
            atomicMax(&smax_i[wm*64+mt*16+r+i2*8], __float_as_int(rmax[mt*2+i2]));
    #pragma unroll
    for (int nt=0; nt<4; nt++)
        #pragma unroll
        for (int q=0; q<2; q++)
            atomicMax(&smax_j[wn*32+nt*8+2*c+q], __float_as_int(cmax[nt*2+q]));
    __syncthreads();
    if (tid<128){
        atomicMax((int*)&g_m[b*NTOK + ib*128 + tid], smax_i[tid]);
        atomicMax((int*)&g_m[b*NTOK + jb*128 + tid], smax_j[tid]);
    }
}

// ---------------------------------------------------------------- launch
extern "C" void kernel_launch(void* const* d_in, const int* in_sizes, int n_in,
                              void* d_out, int out_size) {
    const float* x     = (const float*)d_in[0];
    const float* gamma = (const float*)d_in[1];
    const float* beta  = (const float*)d_in[2];
    const float* w1 = (const float*)d_in[3];
    const float* b1 = (const float*)d_in[4];
    const float* w2 = (const float*)d_in[5];
    const float* b2 = (const float*)d_in[6];
    const float* w3 = (const float*)d_in[7];
    const float* b3 = (const float*)d_in[8];
    const float* w4 = (const float*)d_in[9];
    const float* b4 = (const float*)d_in[10];
    float* out = (float*)d_out;

    cudaFuncSetAttribute(k_gram,      cudaFuncAttributeMaxDynamicSharedMemorySize, DSMEM_SZ);
    cudaFuncSetAttribute(k_ln,        cudaFuncAttributeMaxDynamicSharedMemorySize, LN_SMEM);
    cudaFuncSetAttribute(k_xm,        cudaFuncAttributeMaxDynamicSharedMemorySize, LN_SMEM);
    cudaFuncSetAttribute(k_gemm<0,0>, cudaFuncAttributeMaxDynamicSharedMemorySize, DSMEM_SZ);
    cudaFuncSetAttribute(k_gemm<1,1>, cudaFuncAttributeMaxDynamicSharedMemorySize, DSMEM_SZ);
    cudaFuncSetAttribute(k_gemm<2,1>, cudaFuncAttributeMaxDynamicSharedMemorySize, DSMEM_SZ);
    cudaFuncSetAttribute(k_gemm<0,2>, cudaFuncAttributeMaxDynamicSharedMemorySize, DSMEM_SZ);

    float *wB, *cat, *m1p, *m1r, *tp, *xlp;
    cudaGetSymbolAddress((void**)&wB,  g_wB);
    cudaGetSymbolAddress((void**)&cat, g_cat);
    cudaGetSymbolAddress((void**)&m1p, g_m1p);
    cudaGetSymbolAddress((void**)&m1r, g_m1r);
    cudaGetSymbolAddress((void**)&tp,  g_tp);
    cudaGetSymbolAddress((void**)&xlp, g_xlp);

    // launches 1-5 (keeps gemm1 at profiler index 5)
    k_avg1<<<dim3(8, NB), 192>>>(x);
    k_avg2<<<MTOT*DIMD/NTOK/256, 256>>>();
    k_ln  <<<MTOT/16, 256, LN_SMEM>>>(x, gamma, beta);
    k_gram<<<dim3(36, NB), 256, DSMEM_SZ>>>();
    k_xm  <<<MTOT/16, 256, LN_SMEM>>>(x, w1);

    dim3 gg(DIMD/128, MTOT/128);
    // layer1: m1 = gelu(cat @ w1 + b1)            -> m1p (tf32 P) + m1r (raw)
    k_gemm<0,0><<<gg,256,DSMEM_SZ>>>(cat, wB+W1B, b1, x, nullptr, m1p, m1r, 2*DIMD);
    // w2..w4 transposes (only needed from layer2 on)
    k_tr_rest<<<dim3(DIMD, 3, 3), 256>>>(w2, w3, w4);
    // layer2: t = x*m1*gelu(m1 @ w2 + b2)         -> tp (tf32 P)
    k_gemm<1,1><<<gg,256,DSMEM_SZ>>>(m1p, wB+W2B, b2, x, m1r,     tp,  nullptr, DIMD);
    // layer3: x*l3 = x*gelu(t @ w3 + b3)          -> xlp (tf32 P)
    k_gemm<2,1><<<gg,256,DSMEM_SZ>>>(tp,  wB+W3B, b3, x, nullptr, xlp, nullptr, DIMD);
    // layer4: out = gelu((x*l3) @ w4 + b4)        -> out (row)
    k_gemm<0,2><<<gg,256,DSMEM_SZ>>>(xlp, wB+W4B, b4, x, nullptr, nullptr, out, DIMD);
}

// round 7
// speedup vs baseline: 2.6959x; 1.4427x over previous
#include <cuda_runtime.h>
#include <cuda_fp16.h>
#include <math.h>
#include <stdint.h>

#define DIMD 768
#define NTOK 1024
#define NB   16
#define MTOT (NB*NTOK)   // 16384

// ---------------- scratch (static device globals) --------------------------
__device__ float g_avg[NB*DIMD];
__device__ float g_pav[8*NB*DIMD];
__device__ float g_sq [MTOT];
__device__ float g_m  [MTOT];
__device__ float g_m1r[MTOT*DIMD];         // m1 raw fp32 (gating)
__device__ __half g_cat[MTOT*2*DIMD];      // [A | x+m] P16-format, K=1536
__device__ __half g_Ab [MTOT*DIMD];        // A B16-format (gram j-side)
__device__ __half g_m1p[MTOT*DIMD];        // m1 P16
__device__ __half g_tp [MTOT*DIMD];        // t  P16
__device__ __half g_xlp[MTOT*DIMD];        // x*l3 P16
__device__ __half g_wB [5*DIMD*DIMD];      // weights B16 (w1 uses 2 blocks)
#define W1B 0
#define W2B (2*DIMD*DIMD)
#define W3B (3*DIMD*DIMD)
#define W4B (4*DIMD*DIMD)

// ---------------- helpers ---------------------------------------------------
__device__ __forceinline__ float gelu_exact(float v){ return v * normcdff(v); }
__device__ __forceinline__ uint32_t h2(float lo, float hi){
    __half2 h = __floats2half2_rn(lo, hi);
    return *(uint32_t*)&h;
}
__device__ __forceinline__ float h1r(float x){   // round-trip through fp16
    return __half2float(__float2half_rn(x));
}
__device__ __forceinline__ uint32_t smem_u32(const void* p){
    uint32_t a; asm("{ .reg .u64 t; cvta.to.shared.u64 t, %1; cvt.u32.u64 %0, t; }" : "=r"(a) : "l"(p));
    return a;
}
__device__ __forceinline__ void cpa16(uint32_t dst, const void* src){
    asm volatile("cp.async.cg.shared.global [%0], [%1], 16;" :: "r"(dst), "l"(src));
}
__device__ __forceinline__ void cpa_commit(){ asm volatile("cp.async.commit_group;"); }
__device__ __forceinline__ void cpa_wait1(){ asm volatile("cp.async.wait_group 1;"); }

__device__ __forceinline__ void mma16(float* cc, const uint32_t* a, const uint32_t* b){
    asm volatile("mma.sync.aligned.m16n8k16.row.col.f32.f16.f16.f32 "
       "{%0,%1,%2,%3},{%4,%5,%6,%7},{%8,%9},{%0,%1,%2,%3};"
       : "+f"(cc[0]),"+f"(cc[1]),"+f"(cc[2]),"+f"(cc[3])
       : "r"(a[0]),"r"(a[1]),"r"(a[2]),"r"(a[3]),"r"(b[0]),"r"(b[1]));
}

// smem: 3 stages x (A 8KB + B 8KB) = 48KB
#define STG 8192u
#define SBOFF 24576u
#define DSMEM_SZ 49152
#define LN_SMEM (16*772*4)

// ---------------------------------------------------------------- k_avg
__global__ void k_avg1(const float* __restrict__ x){
    int chunk = blockIdx.x, b = blockIdx.y;
    int t = threadIdx.x;
    const float4* p = (const float4*)(x + ((size_t)b*NTOK + chunk*128)*DIMD) + t;
    float4 s = make_float4(0.f,0.f,0.f,0.f);
    #pragma unroll 4
    for (int i=0;i<128;i++){
        float4 v = p[i*(DIMD/4)];
        s.x+=v.x; s.y+=v.y; s.z+=v.z; s.w+=v.w;
    }
    *((float4*)(g_pav + ((size_t)chunk*NB + b)*DIMD) + t) = s;
}
__global__ void k_avg2(){
    int gid = blockIdx.x*256 + threadIdx.x;
    int b = gid / DIMD, d = gid % DIMD;
    float s = 0.f;
    #pragma unroll
    for (int c=0;c<8;c++) s += g_pav[((size_t)c*NB + b)*DIMD + d];
    g_avg[gid] = s * (1.0f/NTOK);
}

// ---------------------------------------------------------------- k_ln
// A = fp16(avg*sigmoid(LN(x))) -> g_cat (P16 lower K) + g_Ab (B16); sq from rounded A
__global__ void __launch_bounds__(256) k_ln(const float* __restrict__ x,
                                            const float* __restrict__ gamma,
                                            const float* __restrict__ beta){
    extern __shared__ float s[];               // 16 x 772
    int tb = blockIdx.x;
    int tid = threadIdx.x, w = tid>>5, l = tid&31;
    #pragma unroll
    for (int half=0; half<2; half++){
        int trow = w*2 + half;
        int tok  = tb*16 + trow;
        const float* xp = x + (size_t)tok*DIMD;
        float v[24]; float s1=0.f, s2=0.f;
        #pragma unroll
        for (int i=0;i<24;i++){ v[i]=xp[l+32*i]; s1+=v[i]; s2+=v[i]*v[i]; }
        #pragma unroll
        for (int o=16;o;o>>=1){ s1+=__shfl_xor_sync(~0u,s1,o); s2+=__shfl_xor_sync(~0u,s2,o); }
        float mu  = s1*(1.f/DIMD);
        float var = s2*(1.f/DIMD) - mu*mu;
        float rs  = rsqrtf(var + 1e-5f);
        const float* av = g_avg + (tok>>10)*DIMD;
        float asq = 0.f;
        #pragma unroll
        for (int i=0;i<24;i++){
            int d = l + 32*i;
            float y  = (v[i]-mu)*rs*gamma[d] + beta[d];
            float sg = 1.f/(1.f+expf(-y));
            float a  = h1r(av[d]*sg);
            s[trow*772 + d] = a;
            asq += a*a;
        }
        #pragma unroll
        for (int o=16;o;o>>=1) asq += __shfl_xor_sync(~0u,asq,o);
        if (l==0){ g_sq[tok]=asq; g_m[tok]=0.f; }
    }
    __syncthreads();
    int rr = l>>2, c2 = (l&3)*2;
    // P16 store: subtile=16 rows x 16 k, lane word = 8 halfs
    #pragma unroll
    for (int it=0; it<6; it++){
        int ksub = it*8 + w;                   // 0..47
        int kk = ksub*16 + c2;
        uint4 o;
        o.x = h2(s[rr*772+kk],       s[rr*772+kk+1]);
        o.y = h2(s[(rr+8)*772+kk],   s[(rr+8)*772+kk+1]);
        o.z = h2(s[rr*772+kk+8],     s[rr*772+kk+9]);
        o.w = h2(s[(rr+8)*772+kk+8], s[(rr+8)*772+kk+9]);
        *(uint4*)(g_cat + ((size_t)tb*96 + ksub)*256 + l*8) = o;
    }
    // B16 store: subtile=8 n x 16 k, lane word = 4 halfs
    #pragma unroll
    for (int it=0; it<12; it++){
        int subidx = it*8 + w;                 // 0..95
        int nsub = subidx/48, ksub = subidx%48;
        int n = nsub*8 + rr;
        int kk = ksub*16 + c2;
        uint2 o;
        o.x = h2(s[n*772+kk],   s[n*772+kk+1]);
        o.y = h2(s[n*772+kk+8], s[n*772+kk+9]);
        *(uint2*)(g_Ab + (((size_t)(tb*2+nsub))*48 + ksub)*128 + l*4) = o;
    }
}

// ---------------------------------------------------------------- k_xm
// upper half of g_cat = fp16(x+m) P16; folds w1 -> B16 transpose
__global__ void __launch_bounds__(256) k_xm(const float* __restrict__ x,
                                            const float* __restrict__ w1){
    extern __shared__ float s[];   // 16 x 772
    int tb = blockIdx.x;
    int tid = threadIdx.x;
    #pragma unroll
    for (int it=0; it<12; it++){
        int idx = it*256 + tid;
        int row = idx/192, c4 = idx%192;
        int tok = tb*16 + row;
        float4 v = *(const float4*)(x + (size_t)tok*DIMD + c4*4);
        float mm = g_m[tok];
        float* d = s + row*772 + c4*4;
        d[0]=v.x+mm; d[1]=v.y+mm; d[2]=v.z+mm; d[3]=v.w+mm;
    }
    __syncthreads();
    int w = tid>>5, l = tid&31;
    int rr = l>>2, c2 = (l&3)*2;
    #pragma unroll
    for (int it=0; it<6; it++){
        int ksub = it*8 + w;
        int kk = ksub*16 + c2;
        uint4 o;
        o.x = h2(s[rr*772+kk],       s[rr*772+kk+1]);
        o.y = h2(s[(rr+8)*772+kk],   s[(rr+8)*772+kk+1]);
        o.z = h2(s[rr*772+kk+8],     s[rr*772+kk+9]);
        o.w = h2(s[(rr+8)*772+kk+8], s[(rr+8)*772+kk+9]);
        *(uint4*)(g_cat + ((size_t)tb*96 + 48 + ksub)*256 + l*8) = o;
    }
    // folded w1 -> B16 (K=1536): 288 8B-words per block
    #pragma unroll
    for (int it=0; it<2; it++){
        int off = it*256 + tid;
        if (off < 288){
            size_t wd = (size_t)tb*288 + off;
            int sub = (int)(wd>>5), lane = (int)(wd&31);
            int n = (sub/96)*8 + (lane>>2);
            int kk = (sub%96)*16 + (lane&3)*2;
            uint2 o;
            o.x = h2(w1[(size_t)kk*DIMD+n],     w1[(size_t)(kk+1)*DIMD+n]);
            o.y = h2(w1[(size_t)(kk+8)*DIMD+n], w1[(size_t)(kk+9)*DIMD+n]);
            *(uint2*)(g_wB + W1B + wd*4) = o;
        }
    }
}

// ---------------------------------------------------------------- k_tr_rest (w2..w4 -> B16, K=768)
__global__ void k_tr_rest(const float* __restrict__ w2,
                          const float* __restrict__ w3,
                          const float* __restrict__ w4){
    int z = blockIdx.y;
    const float* wsrc = (z==0)? w2 : (z==1)? w3 : w4;
    __half* dst = g_wB + ((z==0)? W2B : (z==1)? W3B : W4B);
    size_t wd = (size_t)blockIdx.x*256 + threadIdx.x;   // 147456 words
    int sub = (int)(wd>>5), lane = (int)(wd&31);
    int n = (sub/48)*8 + (lane>>2);
    int kk = (sub%48)*16 + (lane&3)*2;
    uint2 o;
    o.x = h2(wsrc[(size_t)kk*DIMD+n],     wsrc[(size_t)(kk+1)*DIMD+n]);
    o.y = h2(wsrc[(size_t)(kk+8)*DIMD+n], wsrc[(size_t)(kk+9)*DIMD+n]);
    *(uint2*)(dst + wd*4) = o;
}

// ---------------------------------------------------------------- k_gemm (fp16 fragments)
// EPI 0: gelu   1: gelu*x*m1r   2: gelu*x
// OUT 0: Cp=P16 + Cr=raw row   1: Cp=P16   2: Cr=raw row
template<int EPI, int OUT>
__global__ void __launch_bounds__(256) k_gemm(
    const __half* __restrict__ pA, const __half* __restrict__ pB,
    const float* __restrict__ bias, const float* __restrict__ x,
    const float* __restrict__ m1r, __half* __restrict__ Cp,
    float* __restrict__ Cr, int Ktot)
{
    extern __shared__ float dsm[];
    uint32_t sA = smem_u32(dsm);
    uint32_t sB = sA + SBOFF;
    int tid = threadIdx.x, lane = tid&31;
    int wm = (tid>>5)&1, wn = tid>>6;
    int r = lane>>2, c = lane&3;
    int nb = blockIdx.x, mb = blockIdx.y;
    const int KT  = Ktot/32;
    const int K16 = Ktot>>4;

    float acc[4][4][4];
    #pragma unroll
    for (int a=0;a<4;a++)
      #pragma unroll
      for (int b=0;b<4;b++)
        #pragma unroll
        for (int e=0;e<4;e++) acc[a][b][e]=0.f;

    auto load_stage = [&](int kt){
        int st = kt % 3;
        uint32_t dA = sA + st*STG;
        uint32_t dB = sB + st*STG;
        #pragma unroll
        for (int it=0; it<2; it++){
            int wd = it*256 + tid;             // 0..511
            int rowsub = wd>>6, remA = wd&63;
            cpa16(dA + wd*16, pA + ((size_t)(mb*8+rowsub)*K16 + kt*2)*256 + remA*8);
            int nsub = wd>>5,  remB = wd&31;
            cpa16(dB + wd*16, pB + ((size_t)(nb*16+nsub)*K16 + kt*2)*128 + remB*8);
        }
        cpa_commit();
    };

    load_stage(0); load_stage(1);
    for (int kt=0; kt<KT; kt++){
        cpa_wait1();
        __syncthreads();
        if (kt+2 < KT) load_stage(kt+2); else cpa_commit();
        int st = kt % 3;
        uint32_t bA = sA + st*STG;
        uint32_t bB = sB + st*STG;
        #pragma unroll
        for (int jj=0;jj<2;jj++){
            uint4 af[4]; uint2 bf[4];
            #pragma unroll
            for (int mt=0;mt<4;mt++){
                uint32_t a = bA + (((wm*4+mt)*2+jj)<<9) + (lane<<4);
                asm volatile("ld.shared.v4.b32 {%0,%1,%2,%3},[%4];"
                  : "=r"(af[mt].x),"=r"(af[mt].y),"=r"(af[mt].z),"=r"(af[mt].w) : "r"(a));
            }
            #pragma unroll
            for (int nt=0;nt<4;nt++){
                uint32_t a = bB + (((wn*4+nt)*2+jj)<<8) + (lane<<3);
                asm volatile("ld.shared.v2.b32 {%0,%1},[%2];"
                  : "=r"(bf[nt].x),"=r"(bf[nt].y) : "r"(a));
            }
            #pragma unroll
            for (int mt=0;mt<4;mt++)
                #pragma unroll
                for (int nt=0;nt<4;nt++)
                    mma16(acc[mt][nt], &af[mt].x, &bf[nt].x);
        }
    }

    // epilogue
    #pragma unroll
    for (int mt=0; mt<4; mt++){
        int rp = mb*128 + wm*64 + mt*16 + r;
        float val[4][4];
        #pragma unroll
        for (int nt=0; nt<4; nt++){
            int cg = nb*128 + wn*32 + nt*8 + 2*c;
            float bb0 = __ldg(bias+cg), bb1 = __ldg(bias+cg+1);
            float a0 = gelu_exact(acc[mt][nt][0] + bb0);
            float a1 = gelu_exact(acc[mt][nt][1] + bb1);
            float a2 = gelu_exact(acc[mt][nt][2] + bb0);
            float a3 = gelu_exact(acc[mt][nt][3] + bb1);
            size_t i0 = (size_t)rp*DIMD + cg, i1 = (size_t)(rp+8)*DIMD + cg;
            if (EPI==1){
                float2 xa=*(const float2*)(x+i0),  xb=*(const float2*)(x+i1);
                float2 ma=*(const float2*)(m1r+i0), mz=*(const float2*)(m1r+i1);
                a0*=xa.x*ma.x; a1*=xa.y*ma.y; a2*=xb.x*mz.x; a3*=xb.y*mz.y;
            } else if (EPI==2){
                float2 xa=*(const float2*)(x+i0), xb=*(const float2*)(x+i1);
                a0*=xa.x; a1*=xa.y; a2*=xb.x; a3*=xb.y;
            }
            if (OUT==0 || OUT==2){
                *(float2*)(Cr+i0) = make_float2(a0,a1);
                *(float2*)(Cr+i1) = make_float2(a2,a3);
            }
            val[nt][0]=a0; val[nt][1]=a1; val[nt][2]=a2; val[nt][3]=a3;
        }
        if (OUT<=1){
            #pragma unroll
            for (int ntp=0; ntp<2; ntp++){
                uint4 o;
                o.x = h2(val[2*ntp][0],   val[2*ntp][1]);
                o.y = h2(val[2*ntp][2],   val[2*ntp][3]);
                o.z = h2(val[2*ntp+1][0], val[2*ntp+1][1]);
                o.w = h2(val[2*ntp+1][2], val[2*ntp+1][3]);
                *(uint4*)(Cp + (((size_t)(mb*8+wm*4+mt))*48 + nb*8+wn*2+ntp)*256 + lane*8) = o;
            }
        }
    }
}

// ---------------------------------------------------------------- k_gram (fp16)
__global__ void __launch_bounds__(256) k_gram(){
    extern __shared__ float dsm[];
    uint32_t sA = smem_u32(dsm);
    uint32_t sB = sA + SBOFF;
    __shared__ int   smax_i[128], smax_j[128];
    __shared__ float sqi_s[128], sqj_s[128];

    int tid = threadIdx.x, lane = tid&31;
    int wm = (tid>>5)&1, wn = tid>>6;
    int r = lane>>2, c = lane&3;
    int b = blockIdx.y;
    int tt = blockIdx.x, ib = 0;
    while (tt >= (8-ib)){ tt -= (8-ib); ib++; }
    int jb = ib + tt;

    if (tid<128){
        sqi_s[tid] = g_sq[b*NTOK + ib*128 + tid];
        sqj_s[tid] = g_sq[b*NTOK + jb*128 + tid];
        smax_i[tid]=0; smax_j[tid]=0;
    }

    float acc[4][4][4];
    #pragma unroll
    for (int a=0;a<4;a++)
      #pragma unroll
      for (int bb=0;bb<4;bb++)
        #pragma unroll
        for (int e=0;e<4;e++) acc[a][bb][e]=0.f;

    const int KT = DIMD/32;   // 24
    auto load_stage = [&](int kt){
        int st = kt % 3;
        uint32_t dA = sA + st*STG;
        uint32_t dB = sB + st*STG;
        #pragma unroll
        for (int it=0; it<2; it++){
            int wd = it*256 + tid;
            int rowsub = wd>>6, remA = wd&63;
            cpa16(dA + wd*16, g_cat + ((size_t)(b*64+ib*8+rowsub)*96 + kt*2)*256 + remA*8);
            int nsub = wd>>5,  remB = wd&31;
            cpa16(dB + wd*16, g_Ab + ((size_t)(b*128+jb*16+nsub)*48 + kt*2)*128 + remB*8);
        }
        cpa_commit();
    };

    load_stage(0); load_stage(1);
    for (int kt=0; kt<KT; kt++){
        cpa_wait1();
        __syncthreads();
        if (kt+2 < KT) load_stage(kt+2); else cpa_commit();
        int st = kt % 3;
        uint32_t bA = sA + st*STG;
        uint32_t bB = sB + st*STG;
        #pragma unroll
        for (int jj=0;jj<2;jj++){
            uint4 af[4]; uint2 bf[4];
            #pragma unroll
            for (int mt=0;mt<4;mt++){
                uint32_t a = bA + (((wm*4+mt)*2+jj)<<9) + (lane<<4);
                asm volatile("ld.shared.v4.b32 {%0,%1,%2,%3},[%4];"
                  : "=r"(af[mt].x),"=r"(af[mt].y),"=r"(af[mt].z),"=r"(af[mt].w) : "r"(a));
            }
            #pragma unroll
            for (int nt=0;nt<4;nt++){
                uint32_t a = bB + (((wn*4+nt)*2+jj)<<8) + (lane<<3);
                asm volatile("ld.shared.v2.b32 {%0,%1},[%2];"
                  : "=r"(bf[nt].x),"=r"(bf[nt].y) : "r"(a));
            }
            #pragma unroll
            for (int mt=0;mt<4;mt++)
                #pragma unroll
                for (int nt=0;nt<4;nt++)
                    mma16(acc[mt][nt], &af[mt].x, &bf[nt].x);
        }
    }

    float rmax[8], cmax[8];
    #pragma unroll
    for (int i=0;i<8;i++){ rmax[i]=0.f; cmax[i]=0.f; }
    #pragma unroll
    for (int mt=0; mt<4; mt++){
        #pragma unroll
        for (int i2=0; i2<2; i2++){
            int rl = wm*64 + mt*16 + r + i2*8;
            float si = sqi_s[rl];
            #pragma unroll
            for (int nt=0; nt<4; nt++){
                #pragma unroll
                for (int q=0; q<2; q++){
                    int cl = wn*32 + nt*8 + 2*c + q;
                    float d2 = si + sqj_s[cl] - 2.f*acc[mt][nt][i2*2+q];
                    float dd = sqrtf(fmaxf(d2, 1e-12f));
                    rmax[mt*2+i2] = fmaxf(rmax[mt*2+i2], dd);
                    cmax[nt*2+q]  = fmaxf(cmax[nt*2+q],  dd);
                }
            }
        }
    }
    #pragma unroll
    for (int mt=0; mt<4; mt++)
        #pragma unroll
        for (int i2=0; i2<2; i2++)
            atomicMax(&smax_i[wm*64+mt*16+r+i2*8], __float_as_int(rmax[mt*2+i2]));
    #pragma unroll
    for (int nt=0; nt<4; nt++)
        #pragma unroll
        for (int q=0; q<2; q++)
            atomicMax(&smax_j[wn*32+nt*8+2*c+q], __float_as_int(cmax[nt*2+q]));
    __syncthreads();
    if (tid<128){
        atomicMax((int*)&g_m[b*NTOK + ib*128 + tid], smax_i[tid]);
        atomicMax((int*)&g_m[b*NTOK + jb*128 + tid], smax_j[tid]);
    }
}

// ---------------------------------------------------------------- launch
extern "C" void kernel_launch(void* const* d_in, const int* in_sizes, int n_in,
                              void* d_out, int out_size) {
    const float* x     = (const float*)d_in[0];
    const float* gamma = (const float*)d_in[1];
    const float* beta  = (const float*)d_in[2];
    const float* w1 = (const float*)d_in[3];
    const float* b1 = (const float*)d_in[4];
    const float* w2 = (const float*)d_in[5];
    const float* b2 = (const float*)d_in[6];
    const float* w3 = (const float*)d_in[7];
    const float* b3 = (const float*)d_in[8];
    const float* w4 = (const float*)d_in[9];
    const float* b4 = (const float*)d_in[10];
    float* out = (float*)d_out;

    cudaFuncSetAttribute(k_gram,      cudaFuncAttributeMaxDynamicSharedMemorySize, DSMEM_SZ);
    cudaFuncSetAttribute(k_ln,        cudaFuncAttributeMaxDynamicSharedMemorySize, LN_SMEM);
    cudaFuncSetAttribute(k_xm,        cudaFuncAttributeMaxDynamicSharedMemorySize, LN_SMEM);
    cudaFuncSetAttribute(k_gemm<0,0>, cudaFuncAttributeMaxDynamicSharedMemorySize, DSMEM_SZ);
    cudaFuncSetAttribute(k_gemm<1,1>, cudaFuncAttributeMaxDynamicSharedMemorySize, DSMEM_SZ);
    cudaFuncSetAttribute(k_gemm<2,1>, cudaFuncAttributeMaxDynamicSharedMemorySize, DSMEM_SZ);
    cudaFuncSetAttribute(k_gemm<0,2>, cudaFuncAttributeMaxDynamicSharedMemorySize, DSMEM_SZ);

    __half *wB, *cat, *m1p, *tp, *xlp;
    float *m1r;
    cudaGetSymbolAddress((void**)&wB,  g_wB);
    cudaGetSymbolAddress((void**)&cat, g_cat);
    cudaGetSymbolAddress((void**)&m1p, g_m1p);
    cudaGetSymbolAddress((void**)&m1r, g_m1r);
    cudaGetSymbolAddress((void**)&tp,  g_tp);
    cudaGetSymbolAddress((void**)&xlp, g_xlp);

    k_avg1<<<dim3(8, NB), 192>>>(x);
    k_avg2<<<MTOT*DIMD/NTOK/256, 256>>>();
    k_ln  <<<MTOT/16, 256, LN_SMEM>>>(x, gamma, beta);
    k_gram<<<dim3(36, NB), 256, DSMEM_SZ>>>();
    k_xm  <<<MTOT/16, 256, LN_SMEM>>>(x, w1);

    dim3 gg(DIMD/128, MTOT/128);
    // layer1: m1 = gelu(cat @ w1 + b1)            -> m1p (P16) + m1r (raw)
    k_gemm<0,0><<<gg,256,DSMEM_SZ>>>(cat, wB+W1B, b1, x, nullptr, m1p, m1r, 2*DIMD);
    // w2..w4 transposes
    k_tr_rest<<<dim3(576, 3), 256>>>(w2, w3, w4);
    // layer2: t = x*m1*gelu(m1 @ w2 + b2)         -> tp (P16)
    k_gemm<1,1><<<gg,256,DSMEM_SZ>>>(m1p, wB+W2B, b2, x, m1r,     tp,  nullptr, DIMD);
    // layer3: x*l3 = x*gelu(t @ w3 + b3)          -> xlp (P16)
    k_gemm<2,1><<<gg,256,DSMEM_SZ>>>(tp,  wB+W3B, b3, x, nullptr, xlp, nullptr, DIMD);
    // layer4: out = gelu((x*l3) @ w4 + b4)        -> out (row)
    k_gemm<0,2><<<gg,256,DSMEM_SZ>>>(xlp, wB+W4B, b4, x, nullptr, nullptr, out, DIMD);
}